// round 12
// baseline (speedup 1.0000x reference)
#include <cuda_runtime.h>

#define Bc      128
#define Sc      37
#define Tc      2048
#define Dc      256
#define STc     8
#define Cc      2
#define Fc      (2 * Sc)        // 74
#define MERGEDc (Dc + STc)      // 264
#define SPLIT   4
#define CHUNK   (Tc / SPLIT)    // 512 t per CTA
#define NT1     256
#define W1      (NT1 / 32)      // 8 warps
#define NJT     33              // merge j-tiles (264/8)

// Per-batch partial sums, one row per phase1 CTA:
// [0..36]=sum x, [37..73]=sum mask, [74]=sum valid*time, [75]=sum valid
__device__ float        g_part[Bc][SPLIT][80];
__device__ float        g_combT[MERGEDc][Bc];   // transposed comb
__device__ float        g_clsp[NJT][Bc][Cc];    // per-jtile classifier partials
__device__ unsigned int g_cnt2;                 // headB election; self-resetting

// ---------------------------------------------------------------------------
// Phase 1: warp-per-sensor streaming sums (unchanged from R11)
// ---------------------------------------------------------------------------
__global__ __launch_bounds__(NT1, 6)
void phase1(const float* __restrict__ x,        // [B,S,T]
            const int*   __restrict__ smask,    // [B,S,T]
            const float* __restrict__ time_in)  // [B,T]
{
    const int blk   = blockIdx.x;
    const int b     = blk >> 2;
    const int part  = blk & (SPLIT - 1);
    const int tid   = threadIdx.x;
    const int lane  = tid & 31;
    const int warp  = tid >> 5;
    const int tbase = part * CHUNK;

    __shared__ float ssum[Fc];
    __shared__ int   vmsh[W1][32];
    __shared__ float td[2];

    const float* xb = x     + (size_t)b * Sc * Tc;
    const int*   mb = smask + (size_t)b * Sc * Tc;

    unsigned vmask = 0;

#pragma unroll
    for (int k = 0; k < 5; ++k) {
        const int s = warp + 8 * k;
        if (s < Sc) {
            float xacc = 0.f;
            int   macc = 0;
#pragma unroll
            for (int it = 0; it < 4; ++it) {
                const int t = tbase + it * 128 + lane * 4;
                const float4 xv = __ldg((const float4*)(xb + (size_t)s * Tc + t));
                const int4   mv = __ldg((const int4*)  (mb + (size_t)s * Tc + t));
                // valid[t]==0 => all features at t are 0 => plain sums == masked sums
                xacc += (xv.x + xv.y) + (xv.z + xv.w);
                macc += (mv.x + mv.y) + (mv.z + mv.w);
                unsigned bits = (((xv.x != 0.f) | (mv.x != 0)) ? 1u : 0u)
                              | (((xv.y != 0.f) | (mv.y != 0)) ? 2u : 0u)
                              | (((xv.z != 0.f) | (mv.z != 0)) ? 4u : 0u)
                              | (((xv.w != 0.f) | (mv.w != 0)) ? 8u : 0u);
                vmask |= bits << (it * 4);
            }
            float maccf = (float)macc;
#pragma unroll
            for (int o = 16; o > 0; o >>= 1) {
                xacc  += __shfl_xor_sync(0xFFFFFFFFu, xacc,  o);
                maccf += __shfl_xor_sync(0xFFFFFFFFu, maccf, o);
            }
            if (lane == 0) {
                ssum[s]      = xacc;
                ssum[Sc + s] = maccf;
            }
        }
    }
    vmsh[warp][lane] = (int)vmask;
    __syncthreads();

    if (warp == 0) {
        unsigned v = 0;
#pragma unroll
        for (int w = 0; w < W1; ++w) v |= (unsigned)vmsh[w][lane];
        const float* tb = time_in + (size_t)b * Tc;
        float tsum = 0.f;
        float den  = (float)__popc(v);
#pragma unroll
        for (int it = 0; it < 4; ++it) {
            const float4 tv = __ldg((const float4*)(tb + tbase + it * 128 + lane * 4));
            const unsigned bb = (v >> (it * 4)) & 0xFu;
            tsum += ((bb & 1u) ? tv.x : 0.f) + ((bb & 2u) ? tv.y : 0.f)
                  + ((bb & 4u) ? tv.z : 0.f) + ((bb & 8u) ? tv.w : 0.f);
        }
#pragma unroll
        for (int o = 16; o > 0; o >>= 1) {
            tsum += __shfl_xor_sync(0xFFFFFFFFu, tsum, o);
            den  += __shfl_xor_sync(0xFFFFFFFFu, den,  o);
        }
        if (lane == 0) { td[0] = tsum; td[1] = den; }
    }
    __syncthreads();

    if (tid < Fc)            g_part[b][part][tid]    = ssum[tid];
    else if (tid == Fc)      g_part[b][part][Fc]     = td[0];
    else if (tid == Fc + 1)  g_part[b][part][Fc + 1] = td[1];
}

// ---------------------------------------------------------------------------
// headA: sensor projection + static, weights-stationary over 8 batches/CTA.
// Writes comb TRANSPOSED: g_combT[d][b].
// ---------------------------------------------------------------------------
__global__ __launch_bounds__(256, 1)
void headA(const float* __restrict__ stat_in,   // [B,ST]
           const float* __restrict__ W_sensor,  // [2S,D]
           const float* __restrict__ b_sensor,  // [D]
           const float* __restrict__ W_time,    // [1,D]
           const float* __restrict__ b_time,    // [D]
           const float* __restrict__ W_static,  // [ST,ST]
           const float* __restrict__ b_static)  // [ST]
{
    const int b0  = blockIdx.x * 8;
    const int tid = threadIdx.x;

    __shared__ float sxs[8][76];
    for (int idx = tid; idx < 8 * 76; idx += 256) {
        const int bb = idx / 76, f = idx % 76;
        sxs[bb][f] = (g_part[b0 + bb][0][f] + g_part[b0 + bb][1][f])
                   + (g_part[b0 + bb][2][f] + g_part[b0 + bb][3][f]);
    }
    __syncthreads();

    // main: thread owns one d; each W element loaded once, used for 8 batches
    {
        const int d = tid;
        float acc[8];
#pragma unroll
        for (int bb = 0; bb < 8; ++bb) acc[bb] = 0.f;
#pragma unroll 2
        for (int f = 0; f < Fc; ++f) {
            const float w = __ldg(&W_sensor[f * Dc + d]);
#pragma unroll
            for (int bb = 0; bb < 8; ++bb) acc[bb] += sxs[bb][f] * w;
        }
        const float wt   = __ldg(&W_time[d]);
        const float bias = __ldg(&b_sensor[d]) + __ldg(&b_time[d]);
#pragma unroll
        for (int bb = 0; bb < 8; ++bb) {
            const float den = sxs[bb][Fc + 1];
            const float ts  = sxs[bb][Fc];
            g_combT[d][b0 + bb] = (acc[bb] + ts * wt + den * bias)
                                / fmaxf(den, 1e-9f);
        }
    }
    // static embedding: 64 threads -> (bb, j)
    if (tid < 64) {
        const int bb = tid >> 3, j = tid & 7;
        float a = __ldg(&b_static[j]);
#pragma unroll
        for (int i = 0; i < STc; ++i)
            a += __ldg(&stat_in[(b0 + bb) * STc + i]) * __ldg(&W_static[i * STc + j]);
        g_combT[Dc + j][b0 + bb] = a;
    }
}

// ---------------------------------------------------------------------------
// headB: merge + ReLU + classifier, weights-stationary j-tiles.
// W_merge read ONCE chip-wide. Merge output never materialized.
// ---------------------------------------------------------------------------
__global__ __launch_bounds__(1024, 1)
void headB(const float* __restrict__ W_merge,   // [MERGED,MERGED]
           const float* __restrict__ b_merge,   // [MERGED]
           const float* __restrict__ W_cls,     // [MERGED,C]
           const float* __restrict__ b_cls,     // [C]
           float* __restrict__ out)             // [B,C]
{
    const int jt  = blockIdx.x * 8;
    const int tid = threadIdx.x;
    const int j   = tid >> 7;          // 0..7
    const int b   = tid & 127;         // 0..127

    __shared__ float w_s[MERGEDc][8];  // W_merge[:, jt..jt+8)
    __shared__ float cls_s[8][Bc][Cc];
    __shared__ int   last;

    for (int idx = tid; idx < MERGEDc * 8; idx += 1024) {
        const int i = idx >> 3, jj = idx & 7;
        w_s[i][jj] = __ldg(&W_merge[i * MERGEDc + jt + jj]);
    }
    __syncthreads();

    // merge dot product: smem-broadcast weight x coalesced comb_T
    float acc = 0.f;
#pragma unroll 4
    for (int i = 0; i < MERGEDc; ++i)
        acc += g_combT[i][b] * w_s[i][j];

    const float r = fmaxf(acc + __ldg(&b_merge[jt + j]), 0.f);
    cls_s[j][b][0] = r * __ldg(&W_cls[(jt + j) * Cc + 0]);
    cls_s[j][b][1] = r * __ldg(&W_cls[(jt + j) * Cc + 1]);
    __syncthreads();

    if (tid < 256) {
        const int bb = tid >> 1, c = tid & 1;
        float a = 0.f;
#pragma unroll
        for (int p = 0; p < 8; ++p) a += cls_s[p][bb][c];
        g_clsp[blockIdx.x][bb][c] = a;
        __threadfence();
    }
    __syncthreads();

    // last-CTA election finishes the classifier (tiny tail, fixed-order sums)
    if (tid == 0) {
        const unsigned old = atomicAdd(&g_cnt2, 1u);
        last = (old == NJT - 1);
        if (last) g_cnt2 = 0;          // self-reset for next graph replay
    }
    __syncthreads();
    if (!last) return;
    __threadfence();

    if (tid < 256) {
        const int bb = tid >> 1, c = tid & 1;
        float a = __ldg(&b_cls[c]);
#pragma unroll
        for (int p = 0; p < NJT; ++p) a += g_clsp[p][bb][c];
        out[bb * Cc + c] = a;
    }
}

extern "C" void kernel_launch(void* const* d_in, const int* in_sizes, int n_in,
                              void* d_out, int out_size)
{
    const float* x        = (const float*)d_in[0];
    const float* stat_in  = (const float*)d_in[1];
    const float* time_in  = (const float*)d_in[2];
    const int*   smask    = (const int*)  d_in[3];
    const float* W_sensor = (const float*)d_in[4];
    const float* b_sensor = (const float*)d_in[5];
    const float* W_time   = (const float*)d_in[6];
    const float* b_time   = (const float*)d_in[7];
    const float* W_static = (const float*)d_in[8];
    const float* b_static = (const float*)d_in[9];
    const float* W_merge  = (const float*)d_in[10];
    const float* b_merge  = (const float*)d_in[11];
    const float* W_cls    = (const float*)d_in[12];
    const float* b_cls    = (const float*)d_in[13];
    float* out = (float*)d_out;

    phase1<<<Bc * SPLIT, NT1>>>(x, smask, time_in);
    headA<<<16, 256>>>(stat_in, W_sensor, b_sensor, W_time, b_time,
                       W_static, b_static);
    headB<<<NJT, 1024>>>(W_merge, b_merge, W_cls, b_cls, out);
}

// round 14
// speedup vs baseline: 2.0253x; 2.0253x over previous
#include <cuda_runtime.h>

#define Bc      128
#define Sc      37
#define Tc      2048
#define Dc      256
#define STc     8
#define Cc      2
#define Fc      (2 * Sc)        // 74
#define MERGEDc (Dc + STc)      // 264
#define SPLIT   4
#define CHUNK   (Tc / SPLIT)    // 512 t per CTA
#define NT1     256
#define W1      (NT1 / 32)      // 8 warps
#define KROWS   85              // 74 sx + ts + den + 8 static + 1 const
#define GRID1   (Bc * SPLIT)    // 512 streaming CTAs

// [0..36]=sum x, [37..73]=sum mask, [74]=sum valid*time, [75]=sum valid
__device__ float g_part[Bc][SPLIT][80];
// Composed head matrix (transposed: row = input dim, col = merge output j)
__device__ float g_K[KROWS][MERGEDc];

// ---------------------------------------------------------------------------
// Kernel 1: streaming sums (CTAs 0..511) + head-matrix composition (512..596)
// ---------------------------------------------------------------------------
__global__ __launch_bounds__(NT1, 6)
void phase1(const float* __restrict__ x,        // [B,S,T]
            const int*   __restrict__ smask,    // [B,S,T]
            const float* __restrict__ time_in,  // [B,T]
            const float* __restrict__ W_sensor, // [2S,D]
            const float* __restrict__ b_sensor, // [D]
            const float* __restrict__ W_time,   // [1,D]
            const float* __restrict__ b_time,   // [D]
            const float* __restrict__ W_static, // [ST,ST]
            const float* __restrict__ b_static, // [ST]
            const float* __restrict__ W_merge,  // [MERGED,MERGED]
            const float* __restrict__ b_merge)  // [MERGED]
{
    const int blk = blockIdx.x;
    const int tid = threadIdx.x;

    // =================== prep path: compose K = head matrix ================
    if (blk >= GRID1) {
        const int row = blk - GRID1;          // 0..84
        __shared__ float vec[Dc];
        if (row < 76) {
            // rows 0..73: W_sensor row; 74: W_time; 75: b_sensor+b_time
            for (int d = tid; d < Dc; d += NT1) {
                float v;
                if (row < Fc)        v = __ldg(&W_sensor[row * Dc + d]);
                else if (row == Fc)  v = __ldg(&W_time[d]);
                else                 v = __ldg(&b_sensor[d]) + __ldg(&b_time[d]);
                vec[d] = v;
            }
            __syncthreads();
            for (int jj = tid; jj < MERGEDc; jj += NT1) {
                float a0 = 0.f, a1 = 0.f;
#pragma unroll 8
                for (int d = 0; d < Dc; d += 2) {
                    a0 += vec[d]     * __ldg(&W_merge[d * MERGEDc + jj]);
                    a1 += vec[d + 1] * __ldg(&W_merge[(d + 1) * MERGEDc + jj]);
                }
                g_K[row][jj] = a0 + a1;
            }
        } else if (row < 84) {
            // rows 76..83: static input i -> (W_static compose W_merge tail)
            const int i = row - 76;
            for (int jj = tid; jj < MERGEDc; jj += NT1) {
                float a = 0.f;
#pragma unroll
                for (int st = 0; st < STc; ++st)
                    a += __ldg(&W_static[i * STc + st])
                       * __ldg(&W_merge[(Dc + st) * MERGEDc + jj]);
                g_K[row][jj] = a;
            }
        } else {
            // row 84: constant = b_static compose W_merge tail + b_merge
            for (int jj = tid; jj < MERGEDc; jj += NT1) {
                float a = __ldg(&b_merge[jj]);
#pragma unroll
                for (int st = 0; st < STc; ++st)
                    a += __ldg(&b_static[st])
                       * __ldg(&W_merge[(Dc + st) * MERGEDc + jj]);
                g_K[row][jj] = a;
            }
        }
        return;
    }

    // =================== streaming path (unchanged from R11) ===============
    const int b     = blk >> 2;
    const int part  = blk & (SPLIT - 1);
    const int lane  = tid & 31;
    const int warp  = tid >> 5;
    const int tbase = part * CHUNK;

    __shared__ float ssum[Fc];
    __shared__ int   vmsh[W1][32];
    __shared__ float td[2];

    const float* xb = x     + (size_t)b * Sc * Tc;
    const int*   mb = smask + (size_t)b * Sc * Tc;

    unsigned vmask = 0;

#pragma unroll
    for (int k = 0; k < 5; ++k) {
        const int s = warp + 8 * k;
        if (s < Sc) {
            float xacc = 0.f;
            int   macc = 0;
#pragma unroll
            for (int it = 0; it < 4; ++it) {
                const int t = tbase + it * 128 + lane * 4;
                const float4 xv = __ldg((const float4*)(xb + (size_t)s * Tc + t));
                const int4   mv = __ldg((const int4*)  (mb + (size_t)s * Tc + t));
                // valid[t]==0 => all features at t are 0 => plain sums == masked
                xacc += (xv.x + xv.y) + (xv.z + xv.w);
                macc += (mv.x + mv.y) + (mv.z + mv.w);
                unsigned bits = (((xv.x != 0.f) | (mv.x != 0)) ? 1u : 0u)
                              | (((xv.y != 0.f) | (mv.y != 0)) ? 2u : 0u)
                              | (((xv.z != 0.f) | (mv.z != 0)) ? 4u : 0u)
                              | (((xv.w != 0.f) | (mv.w != 0)) ? 8u : 0u);
                vmask |= bits << (it * 4);
            }
            float maccf = (float)macc;
#pragma unroll
            for (int o = 16; o > 0; o >>= 1) {
                xacc  += __shfl_xor_sync(0xFFFFFFFFu, xacc,  o);
                maccf += __shfl_xor_sync(0xFFFFFFFFu, maccf, o);
            }
            if (lane == 0) {
                ssum[s]      = xacc;
                ssum[Sc + s] = maccf;
            }
        }
    }
    vmsh[warp][lane] = (int)vmask;
    __syncthreads();

    if (warp == 0) {
        unsigned v = 0;
#pragma unroll
        for (int w = 0; w < W1; ++w) v |= (unsigned)vmsh[w][lane];
        const float* tb = time_in + (size_t)b * Tc;
        float tsum = 0.f;
        float den  = (float)__popc(v);
#pragma unroll
        for (int it = 0; it < 4; ++it) {
            const float4 tv = __ldg((const float4*)(tb + tbase + it * 128 + lane * 4));
            const unsigned bb = (v >> (it * 4)) & 0xFu;
            tsum += ((bb & 1u) ? tv.x : 0.f) + ((bb & 2u) ? tv.y : 0.f)
                  + ((bb & 4u) ? tv.z : 0.f) + ((bb & 8u) ? tv.w : 0.f);
        }
#pragma unroll
        for (int o = 16; o > 0; o >>= 1) {
            tsum += __shfl_xor_sync(0xFFFFFFFFu, tsum, o);
            den  += __shfl_xor_sync(0xFFFFFFFFu, den,  o);
        }
        if (lane == 0) { td[0] = tsum; td[1] = den; }
    }
    __syncthreads();

    if (tid < Fc)            g_part[b][part][tid]    = ssum[tid];
    else if (tid == Fc)      g_part[b][part][Fc]     = td[0];
    else if (tid == Fc + 1)  g_part[b][part][Fc + 1] = td[1];
}

// ---------------------------------------------------------------------------
// Kernel 2: per-batch head via composed K — single-stage, 128 CTAs
// ---------------------------------------------------------------------------
__global__ __launch_bounds__(256, 1)
void head(const float* __restrict__ stat_in,   // [B,ST]
          const float* __restrict__ W_cls,     // [MERGED,C]
          const float* __restrict__ b_cls,     // [C]
          float* __restrict__ out)             // [B,C]
{
    const int b    = blockIdx.x;
    const int tid  = threadIdx.x;
    const int lane = tid & 31;

    __shared__ float u[84];          // 0..75: pooled sums/ts/den; 76..83: static in
    __shared__ float combr[MERGEDc];

    if (tid < 76) {
        u[tid] = (g_part[b][0][tid] + g_part[b][1][tid])
               + (g_part[b][2][tid] + g_part[b][3][tid]);
    } else if (tid < 84) {
        u[tid] = __ldg(&stat_in[b * STc + (tid - 76)]);
    }
    __syncthreads();

    const float invden = 1.f / fmaxf(u[75], 1e-9f);

    for (int jj = tid; jj < MERGEDc; jj += 256) {
        float a0 = 0.f, a1 = 0.f;
#pragma unroll 4
        for (int f = 0; f < 76; f += 2) {
            a0 += u[f]     * __ldg(&g_K[f][jj]);
            a1 += u[f + 1] * __ldg(&g_K[f + 1][jj]);
        }
        float z = (a0 + a1) * invden + __ldg(&g_K[84][jj]);
#pragma unroll
        for (int i = 0; i < STc; ++i)
            z += u[76 + i] * __ldg(&g_K[76 + i][jj]);
        combr[jj] = fmaxf(z, 0.f);
    }
    __syncthreads();

    if (tid < 32) {
        float c0 = 0.f, c1 = 0.f;
        for (int i = lane; i < MERGEDc; i += 32) {
            const float v = combr[i];
            c0 += v * __ldg(&W_cls[i * Cc + 0]);
            c1 += v * __ldg(&W_cls[i * Cc + 1]);
        }
#pragma unroll
        for (int o = 16; o > 0; o >>= 1) {
            c0 += __shfl_xor_sync(0xFFFFFFFFu, c0, o);
            c1 += __shfl_xor_sync(0xFFFFFFFFu, c1, o);
        }
        if (lane == 0) {
            out[b * Cc + 0] = c0 + __ldg(&b_cls[0]);
            out[b * Cc + 1] = c1 + __ldg(&b_cls[1]);
        }
    }
}

extern "C" void kernel_launch(void* const* d_in, const int* in_sizes, int n_in,
                              void* d_out, int out_size)
{
    const float* x        = (const float*)d_in[0];
    const float* stat_in  = (const float*)d_in[1];
    const float* time_in  = (const float*)d_in[2];
    const int*   smask    = (const int*)  d_in[3];
    const float* W_sensor = (const float*)d_in[4];
    const float* b_sensor = (const float*)d_in[5];
    const float* W_time   = (const float*)d_in[6];
    const float* b_time   = (const float*)d_in[7];
    const float* W_static = (const float*)d_in[8];
    const float* b_static = (const float*)d_in[9];
    const float* W_merge  = (const float*)d_in[10];
    const float* b_merge  = (const float*)d_in[11];
    const float* W_cls    = (const float*)d_in[12];
    const float* b_cls    = (const float*)d_in[13];
    float* out = (float*)d_out;

    phase1<<<GRID1 + KROWS, NT1>>>(x, smask, time_in,
                                   W_sensor, b_sensor, W_time, b_time,
                                   W_static, b_static, W_merge, b_merge);
    head<<<Bc, 256>>>(stat_in, W_cls, b_cls, out);
}

// round 15
// speedup vs baseline: 2.0805x; 1.0273x over previous
#include <cuda_runtime.h>

#define Bc      128
#define Sc      37
#define Tc      2048
#define Dc      256
#define STc     8
#define Cc      2
#define Fc      (2 * Sc)        // 74
#define MERGEDc (Dc + STc)      // 264
#define SPLIT   4
#define CHUNK   (Tc / SPLIT)    // 512 t per CTA
#define NT      256
#define W1      (NT / 32)       // 8 warps
#define GRID1   (Bc * SPLIT)    // 512 streaming CTAs

// [0..36]=sum x, [37..73]=sum mask, [74]=sum valid*time, [75]=sum valid
__device__ float        g_part[Bc][SPLIT][80];
__device__ unsigned int g_cnt[Bc];   // zero-init; consumer resets after consuming

__global__ __launch_bounds__(NT, 4)
void fused_pc(const float* __restrict__ x,        // [B,S,T]
              const int*   __restrict__ smask,    // [B,S,T]
              const float* __restrict__ time_in,  // [B,T]
              const float* __restrict__ stat_in,  // [B,ST]
              const float* __restrict__ W_sensor, // [2S,D]
              const float* __restrict__ b_sensor, // [D]
              const float* __restrict__ W_time,   // [1,D]
              const float* __restrict__ b_time,   // [D]
              const float* __restrict__ W_static, // [ST,ST]
              const float* __restrict__ b_static, // [ST]
              const float* __restrict__ W_merge,  // [MERGED,MERGED]
              const float* __restrict__ b_merge,  // [MERGED]
              const float* __restrict__ W_cls,    // [MERGED,C]
              const float* __restrict__ b_cls,    // [C]
              float* __restrict__ out)            // [B,C]
{
    const int blk  = blockIdx.x;
    const int tid  = threadIdx.x;
    const int lane = tid & 31;
    const int warp = tid >> 5;

    if (blk < GRID1) {
        // =================================================================
        // PRODUCER: warp-per-sensor streaming sums (R11-proven)
        // =================================================================
        const int b     = blk >> 2;
        const int part  = blk & (SPLIT - 1);
        const int tbase = part * CHUNK;

        __shared__ float ssum[Fc];
        __shared__ int   vmsh[W1][32];
        __shared__ float td[2];

        const float* xb = x     + (size_t)b * Sc * Tc;
        const int*   mb = smask + (size_t)b * Sc * Tc;

        unsigned vmask = 0;

#pragma unroll
        for (int k = 0; k < 5; ++k) {
            const int s = warp + 8 * k;
            if (s < Sc) {
                float xacc = 0.f;
                int   macc = 0;
#pragma unroll
                for (int it = 0; it < 4; ++it) {
                    const int t = tbase + it * 128 + lane * 4;
                    const float4 xv = __ldg((const float4*)(xb + (size_t)s * Tc + t));
                    const int4   mv = __ldg((const int4*)  (mb + (size_t)s * Tc + t));
                    // valid[t]==0 => all features 0 => plain sums == masked sums
                    xacc += (xv.x + xv.y) + (xv.z + xv.w);
                    macc += (mv.x + mv.y) + (mv.z + mv.w);
                    unsigned bits = (((xv.x != 0.f) | (mv.x != 0)) ? 1u : 0u)
                                  | (((xv.y != 0.f) | (mv.y != 0)) ? 2u : 0u)
                                  | (((xv.z != 0.f) | (mv.z != 0)) ? 4u : 0u)
                                  | (((xv.w != 0.f) | (mv.w != 0)) ? 8u : 0u);
                    vmask |= bits << (it * 4);
                }
                float maccf = (float)macc;
#pragma unroll
                for (int o = 16; o > 0; o >>= 1) {
                    xacc  += __shfl_xor_sync(0xFFFFFFFFu, xacc,  o);
                    maccf += __shfl_xor_sync(0xFFFFFFFFu, maccf, o);
                }
                if (lane == 0) {
                    ssum[s]      = xacc;
                    ssum[Sc + s] = maccf;
                }
            }
        }
        vmsh[warp][lane] = (int)vmask;
        __syncthreads();

        if (warp == 0) {
            unsigned v = 0;
#pragma unroll
            for (int w = 0; w < W1; ++w) v |= (unsigned)vmsh[w][lane];
            const float* tb = time_in + (size_t)b * Tc;
            float tsum = 0.f;
            float den  = (float)__popc(v);
#pragma unroll
            for (int it = 0; it < 4; ++it) {
                const float4 tv = __ldg((const float4*)(tb + tbase + it * 128 + lane * 4));
                const unsigned bb = (v >> (it * 4)) & 0xFu;
                tsum += ((bb & 1u) ? tv.x : 0.f) + ((bb & 2u) ? tv.y : 0.f)
                      + ((bb & 4u) ? tv.z : 0.f) + ((bb & 8u) ? tv.w : 0.f);
            }
#pragma unroll
            for (int o = 16; o > 0; o >>= 1) {
                tsum += __shfl_xor_sync(0xFFFFFFFFu, tsum, o);
                den  += __shfl_xor_sync(0xFFFFFFFFu, den,  o);
            }
            if (lane == 0) { td[0] = tsum; td[1] = den; }
        }
        __syncthreads();

        if (tid < Fc) {
            g_part[b][part][tid] = ssum[tid];
            __threadfence();                       // publish my store
        } else if (tid == Fc) {
            g_part[b][part][Fc] = td[0];
            __threadfence();
        } else if (tid == Fc + 1) {
            g_part[b][part][Fc + 1] = td[1];
            __threadfence();
        }
        __syncthreads();                           // order fences before release
        if (tid == 0) atomicAdd(&g_cnt[b], 1u);    // release arrive
        return;
    }

    // =====================================================================
    // CONSUMER: one CTA per batch; waits for its 4 producers, runs head
    // =====================================================================
    const int b = blk - GRID1;

    __shared__ float  sx[76];
    __shared__ float  comb[MERGEDc];
    __shared__ float  combr[MERGEDc];
    __shared__ float4 mpart[4][66];   // merge partials, float4-typed (aligned)

    if (tid == 0) {
        while (atomicAdd(&g_cnt[b], 0u) < SPLIT) { }   // spin (L2 atomic poll)
        g_cnt[b] = 0;                 // self-reset; all producers already arrived
        __threadfence();              // acquire side
    }
    __syncthreads();

    if (tid < 76) {
        sx[tid] = (g_part[b][0][tid] + g_part[b][1][tid])
                + (g_part[b][2][tid] + g_part[b][3][tid]);
    }
    __syncthreads();

    const float denomR = sx[Fc + 1];
    const float invden = 1.f / fmaxf(denomR, 1e-9f);
    const float tsumR  = sx[Fc];

    // ---- sensor projection: thread owns d (coalesced W_sensor columns)
    {
        const int d = tid;
        float a0 = 0.f, a1 = 0.f;
#pragma unroll 8
        for (int f = 0; f < Fc; f += 2) {
            a0 += sx[f]     * __ldg(&W_sensor[f * Dc + d]);
            a1 += sx[f + 1] * __ldg(&W_sensor[(f + 1) * Dc + d]);
        }
        float a = a0 + a1
                + tsumR  * __ldg(&W_time[d])
                + denomR * (__ldg(&b_sensor[d]) + __ldg(&b_time[d]));
        comb[d] = a * invden;
    }
    if (tid < STc) {
        const int j = tid;
        float a = __ldg(&b_static[j]);
#pragma unroll
        for (int i = 0; i < STc; ++i)
            a += __ldg(&stat_in[b * STc + i]) * __ldg(&W_static[i * STc + j]);
        comb[Dc + j] = a;
    }
    __syncthreads();

    // ---- merge: 4 i-groups (66 each) x 66 j-quads, float4
    {
        const int g  = tid >> 6;          // 0..3
        const int q  = tid & 63;          // 0..63
        const int i0 = g * 66;
        float4 acc = make_float4(0.f, 0.f, 0.f, 0.f);
#pragma unroll 6
        for (int k = 0; k < 66; ++k) {
            const float  c = comb[i0 + k];
            const float4 w = __ldg((const float4*)(W_merge + (i0 + k) * MERGEDc) + q);
            acc.x += c * w.x; acc.y += c * w.y;
            acc.z += c * w.z; acc.w += c * w.w;
        }
        mpart[g][q] = acc;

        if (tid < 8) {                    // tail quads 64,65 for all 4 groups
            const int gg  = tid >> 1;
            const int qq  = 64 + (tid & 1);
            const int ii0 = gg * 66;
            float4 a2 = make_float4(0.f, 0.f, 0.f, 0.f);
#pragma unroll 6
            for (int k = 0; k < 66; ++k) {
                const float  c = comb[ii0 + k];
                const float4 w = __ldg((const float4*)(W_merge + (ii0 + k) * MERGEDc) + qq);
                a2.x += c * w.x; a2.y += c * w.y;
                a2.z += c * w.z; a2.w += c * w.w;
            }
            mpart[gg][qq] = a2;
        }
    }
    __syncthreads();

    {
        const float* m0 = (const float*)mpart[0];
        const float* m1 = (const float*)mpart[1];
        const float* m2 = (const float*)mpart[2];
        const float* m3 = (const float*)mpart[3];
        for (int j = tid; j < MERGEDc; j += NT) {
            float a = __ldg(&b_merge[j]) + (m0[j] + m1[j]) + (m2[j] + m3[j]);
            combr[j] = fmaxf(a, 0.f);
        }
    }
    __syncthreads();

    if (tid < 32) {
        float c0 = 0.f, c1 = 0.f;
        for (int i = lane; i < MERGEDc; i += 32) {
            const float v = combr[i];
            c0 += v * __ldg(&W_cls[i * Cc + 0]);
            c1 += v * __ldg(&W_cls[i * Cc + 1]);
        }
#pragma unroll
        for (int o = 16; o > 0; o >>= 1) {
            c0 += __shfl_xor_sync(0xFFFFFFFFu, c0, o);
            c1 += __shfl_xor_sync(0xFFFFFFFFu, c1, o);
        }
        if (lane == 0) {
            out[b * Cc + 0] = c0 + __ldg(&b_cls[0]);
            out[b * Cc + 1] = c1 + __ldg(&b_cls[1]);
        }
    }
}

extern "C" void kernel_launch(void* const* d_in, const int* in_sizes, int n_in,
                              void* d_out, int out_size)
{
    const float* x        = (const float*)d_in[0];
    const float* stat_in  = (const float*)d_in[1];
    const float* time_in  = (const float*)d_in[2];
    const int*   smask    = (const int*)  d_in[3];
    const float* W_sensor = (const float*)d_in[4];
    const float* b_sensor = (const float*)d_in[5];
    const float* W_time   = (const float*)d_in[6];
    const float* b_time   = (const float*)d_in[7];
    const float* W_static = (const float*)d_in[8];
    const float* b_static = (const float*)d_in[9];
    const float* W_merge  = (const float*)d_in[10];
    const float* b_merge  = (const float*)d_in[11];
    const float* W_cls    = (const float*)d_in[12];
    const float* b_cls    = (const float*)d_in[13];
    float* out = (float*)d_out;

    fused_pc<<<GRID1 + Bc, NT>>>(x, smask, time_in, stat_in,
                                 W_sensor, b_sensor, W_time, b_time,
                                 W_static, b_static, W_merge, b_merge,
                                 W_cls, b_cls, out);
}